// round 17
// baseline (speedup 1.0000x reference)
#include <cuda_runtime.h>
#include <cuda_fp16.h>

// Fixed problem shapes
#define NROIS 1024
#define CCH   512
#define HH    38
#define WW    50
#define HWSZ  (HH * WW)          // 1900
#define PRE   14                 // pooling_size * 2
#define PS    7

#define THREADS  128
#define NWARPS   (THREADS / 32)
#define NTASKS   49              // 49 windows (this CTA owns 256 channels)
#define CHB      256             // channels per CTA
#define SOUT_PAD 264             // halves per window row: 528B (16B-aligned), 2-way LDS max

// Transposed feature map in fp16: [cell = y*W + x][channel], 1.94 MB (L2-resident).
__device__ __align__(16) __half g_trh[HWSZ * CCH];

// ---------------- transpose+convert kernel: [C][H*W] fp32 -> [H*W][C] fp16 ----------------
__global__ __launch_bounds__(256)
void transpose_kernel(const float* __restrict__ bottom)
{
    __shared__ float t[64][33];
    const int c0 = blockIdx.x * 32;     // cell tile base
    const int h0 = blockIdx.y * 64;     // channel tile base
    const int tx = threadIdx.x;         // 0..31
    const int ty = threadIdx.y;         // 0..7

#pragma unroll
    for (int i = 0; i < 8; i++) {
        int ch = h0 + ty + i * 8;
        int cc = c0 + tx;
        t[ty + i * 8][tx] = (cc < HWSZ) ? bottom[ch * HWSZ + cc] : 0.0f;
    }
    __syncthreads();
#pragma unroll
    for (int i = 0; i < 4; i++) {
        int cc = c0 + ty + i * 8;
        if (cc < HWSZ) {
            __half2 v = __floats2half2_rn(t[2 * tx][ty + i * 8], t[2 * tx + 1][ty + i * 8]);
            *(__half2*)&g_trh[cc * CCH + h0 + 2 * tx] = v;
        }
    }
    asm volatile("griddepcontrol.launch_dependents;" ::: "memory");
}

// ---------------- main kernel: one CTA per (ROI, channel-half) ----------------
__device__ __forceinline__ float grid_coord(float lo, float hi, float L, int j) {
    float t0 = (hi - lo) / L;
    float t2 = (lo + hi - L) / L;
    float base = -1.0f + (float)j * (2.0f / 13.0f);
    float g = t0 * base + t2;
    return (g + 1.0f) * 0.5f * L;
}

// Per-axis bilinear params (identical arithmetic to previous rounds).
__device__ __forceinline__ void axis_params(float lo, float hi, int Li, int j,
                                            int& i0c, int& i1c, float& w0, float& w1)
{
    float ic = grid_coord(lo, hi, (float)Li, j);
    float f  = floorf(ic);
    float a  = ic - f;
    int i0 = (int)f;
    int i1 = i0 + 1;
    i0c = min(max(i0, 0), Li);
    i1c = min(max(i1, 0), Li);
    w0 = (i0 >= 0 && i0 <= Li) ? (1.0f - a) : 0.0f;
    w1 = (i1 >= 0 && i1 <= Li) ? a : 0.0f;
}

__device__ __forceinline__ __half2 u2h(unsigned u) { return *(__half2*)&u; }

// Issue the 4 corner loads for one sample (no consumption).
__device__ __forceinline__ void load8(const __half* __restrict__ trpb,
                                      uint4 rec, uint4 c[4])
{
    const int a00 = (int)(rec.x & 0xFFFFu) << 9;
    const int a01 = (int)(rec.x >> 16)     << 9;
    const int a10 = (int)(rec.y & 0xFFFFu) << 9;
    const int a11 = (int)(rec.y >> 16)     << 9;
    c[0] = __ldg((const uint4*)(trpb + a00));
    c[1] = __ldg((const uint4*)(trpb + a01));
    c[2] = __ldg((const uint4*)(trpb + a10));
    c[3] = __ldg((const uint4*)(trpb + a11));
}

// Consume 4 corner vectors with this sample's weights.
__device__ __forceinline__ void fma8(uint4 rec, const uint4 c[4],
                                     __half2 acc[4], bool first)
{
    const __half2 p01 = u2h(rec.z);       // (w00, w01)
    const __half2 p23 = u2h(rec.w);       // (w10, w11)
    const __half2 w0 = __low2half2(p01), w1 = __high2half2(p01);
    const __half2 w2 = __low2half2(p23), w3 = __high2half2(p23);
    const unsigned* u0 = (const unsigned*)&c[0];
    const unsigned* u1 = (const unsigned*)&c[1];
    const unsigned* u2p = (const unsigned*)&c[2];
    const unsigned* u3 = (const unsigned*)&c[3];
#pragma unroll
    for (int k = 0; k < 4; k++) {
        __half2 v = __hmul2(w0, u2h(u0[k]));
        v = __hfma2(w1, u2h(u1[k]), v);
        v = __hfma2(w2, u2h(u2p[k]), v);
        v = __hfma2(w3, u2h(u3[k]), v);
        acc[k] = first ? v : __hmax2(acc[k], v);
    }
}

__global__ __launch_bounds__(THREADS, 7)
void crop_pool_kernel(const float* __restrict__ rois,
                      float* __restrict__ out)
{
    __shared__ uint4 srec[PRE * PRE];     // fused: cells u16x4 + 4 weights (half)
    __shared__ __align__(16) __half sout_h[NTASKS * SOUT_PAD];   // ~25.3KB

    const int roi    = blockIdx.x >> 1;
    const int chbase = (blockIdx.x & 1) * CHB;
    const int tid    = threadIdx.x;

    // ---- Single setup phase: each record thread computes its own axis math ----
#pragma unroll
    for (int sidb = 0; sidb < 2; sidb++) {
        int sid = tid + sidb * THREADS;
        if (sid < PRE * PRE) {
            const int jy = sid / PRE;
            const int jx = sid - jy * PRE;
            const float xlo = rois[roi * 5 + 1] * (1.0f / 16.0f);
            const float ylo = rois[roi * 5 + 2] * (1.0f / 16.0f);
            const float xhi = rois[roi * 5 + 3] * (1.0f / 16.0f);
            const float yhi = rois[roi * 5 + 4] * (1.0f / 16.0f);

            int x0, x1, y0, y1;
            float wx0, wx1, wy0, wy1;
            axis_params(xlo, xhi, WW - 1, jx, x0, x1, wx0, wx1);
            axis_params(ylo, yhi, HH - 1, jy, y0, y1, wy0, wy1);

            uint4 r;
            r.x = (unsigned)(y0 * WW + x0) | ((unsigned)(y0 * WW + x1) << 16);
            r.y = (unsigned)(y1 * WW + x0) | ((unsigned)(y1 * WW + x1) << 16);
            __half2 p01 = __floats2half2_rn(wy0 * wx0, wy0 * wx1);
            __half2 p23 = __floats2half2_rn(wy1 * wx0, wy1 * wx1);
            r.z = *(unsigned*)&p01;
            r.w = *(unsigned*)&p23;
            srec[sid] = r;
        }
    }
    __syncthreads();

    // PDL: wait for transpose grid's stores before reading g_trh
    asm volatile("griddepcontrol.wait;" ::: "memory");

    const int warp = tid >> 5;
    const int lane = tid & 31;

    // ---- Compute phase: 49 window-tasks, pairwise-pipelined samples ----
    const int choff  = lane * 8;                       // local half-offset (16B/lane)
    const __half* __restrict__ trpb = g_trh + chbase + choff;

    for (int win = warp; win < NTASKS; win += NWARPS) {
        const int py  = win / 7;
        const int px  = win - py * 7;
        const int s00 = (2 * py) * PRE + 2 * px;

        // sample ids: s0=(0,0) s1=(0,1) s2=(1,0) s3=(1,1) of the 2x2 window
        const uint4 r0 = srec[s00];
        const uint4 r1 = srec[s00 + 1];
        const uint4 r2 = srec[s00 + PRE];
        const uint4 r3 = srec[s00 + PRE + 1];

        __half2 m2[4];
        uint4 ca[4], cb[4];
        // pair 1: issue both sample loads, then consume
        load8(trpb, r0, ca);
        load8(trpb, r1, cb);
        fma8(r0, ca, m2, true);
        // pair 2 loads issued while pair-1 FMAs retire
        load8(trpb, r2, ca);
        fma8(r1, cb, m2, false);
        load8(trpb, r3, cb);
        fma8(r2, ca, m2, false);
        fma8(r3, cb, m2, false);

        *(uint4*)(&sout_h[win * SOUT_PAD + choff]) = *(uint4*)m2;
    }
    __syncthreads();

    // ---- Copy phase: shuffle-widened 128B main runs + parity-aware float2 tail ----
    const int oL    = lane & 15;
    const int halfp = lane >> 4;
    float* ob = out + (size_t)roi * (CCH * PS * PS) + (size_t)chbase * 49;

    for (int it = warp; it < CHB / 4; it += NWARPS) {
        const int c0 = it * 4;
        const __half* colbase = &sout_h[c0 + 2 * halfp];

        // main: o = 0..31 via two strided half2 reads + 2 shuffles
        unsigned a = *(const unsigned*)&colbase[(oL)      * SOUT_PAD];
        unsigned b = *(const unsigned*)&colbase[(oL + 16) * SOUT_PAD];
        unsigned ax = __shfl_xor_sync(0xffffffffu, a, 16);
        unsigned bx = __shfl_xor_sync(0xffffffffu, b, 16);
        unsigned p0 = (lane < 16) ? a  : bx;
        unsigned p1 = (lane < 16) ? ax : b;
        float2 f0 = __half22float2(u2h(p0));
        float2 f1 = __half22float2(u2h(p1));
        __stcs(&ob[(c0 + 0) * 49 + lane], f0.x);   // 128B contiguous run
        __stcs(&ob[(c0 + 1) * 49 + lane], f0.y);
        __stcs(&ob[(c0 + 2) * 49 + lane], f1.x);
        __stcs(&ob[(c0 + 3) * 49 + lane], f1.y);

        // tail: o = 32..48 as parity-aligned float2 runs (+1 scalar per channel).
        {
            const int q = lane >> 3;          // 0..3 -> channel c0+q
            const int i = lane & 7;           // pair index 0..7
            const int cq = c0 + q;
            const int oddc = cq & 1;
            const int o = (oddc ? 33 : 32) + 2 * i;
            const __half* colq = &sout_h[cq];
            __half h0 = colq[o * SOUT_PAD];
            __half h1 = colq[(o + 1) * SOUT_PAD];
            float2 fv = make_float2(__half2float(h0), __half2float(h1));
            *(float2*)&ob[cq * 49 + o] = fv;  // (cq*49 + o) is even -> 8B aligned
            if (i == 0) {
                const int os = oddc ? 32 : 48;
                __stcs(&ob[cq * 49 + os], __half2float(colq[os * SOUT_PAD]));
            }
        }
    }
}

extern "C" void kernel_launch(void* const* d_in, const int* in_sizes, int n_in,
                              void* d_out, int out_size)
{
    const float* bottom = (const float*)d_in[0];
    const float* rois   = (const float*)d_in[1];
    float* out = (float*)d_out;

    // transpose: 64-ch x 32-cell tiles
    dim3 tgrid((HWSZ + 31) / 32, CCH / 64);
    transpose_kernel<<<tgrid, dim3(32, 8)>>>(bottom);

    // crop kernel with PDL: setup overlaps the transpose tail.
    cudaLaunchConfig_t cfg = {};
    cfg.gridDim  = dim3(NROIS * 2, 1, 1);
    cfg.blockDim = dim3(THREADS, 1, 1);
    cfg.dynamicSmemBytes = 0;
    cfg.stream = 0;
    cudaLaunchAttribute attrs[1];
    attrs[0].id = cudaLaunchAttributeProgrammaticStreamSerialization;
    attrs[0].val.programmaticStreamSerializationAllowed = 1;
    cfg.attrs = attrs;
    cfg.numAttrs = 1;
    cudaLaunchKernelEx(&cfg, crop_pool_kernel, rois, out);
}